// round 5
// baseline (speedup 1.0000x reference)
#include <cuda_runtime.h>
#include <cuda_fp16.h>
#include <cstdint>

// AxialAttention: 512 independent attention problems of [S=512, c=64].
// B' = outer*8 + W; q/k/v/out element (B', s, c) at outer*262144 + s*512 + W*64 + c.
// attn output [B',512,512] contiguous, placed after `out` in d_out.
// 16 query rows per CTA, 8 warps x 8-col slices, register-resident scores,
// fp16 m16n8k16 (QK^T) + m16n8k8 (PV), 3 CTAs/SM.

#define QSTRH 72           // Q smem row stride (halves)
#define KSTR 72            // K smem row stride (floats)
#define VSTR 76            // V smem row stride (floats)
#define QROWS 16
#define KVBUF (64*VSTR)
#define QFLOATS (QROWS*QSTRH/2)         // 576
#define RED_OFF (QFLOATS + 2*KVBUF)
#define SMEM_FLOATS (RED_OFF + 260)
#define OPSTR 72
#define NEG_INF __int_as_float(0xff800000)

__device__ __forceinline__ uint32_t packh2(float a, float b) {
    __half2 h = __floats2half2_rn(a, b);
    return *reinterpret_cast<uint32_t*>(&h);
}

__device__ __forceinline__ void mma16(float* c,
        uint32_t a0, uint32_t a1, uint32_t a2, uint32_t a3,
        uint32_t b0, uint32_t b1) {
    asm volatile(
        "mma.sync.aligned.m16n8k16.row.col.f32.f16.f16.f32 "
        "{%0,%1,%2,%3},{%4,%5,%6,%7},{%8,%9},{%0,%1,%2,%3};\n"
        : "+f"(c[0]), "+f"(c[1]), "+f"(c[2]), "+f"(c[3])
        : "r"(a0), "r"(a1), "r"(a2), "r"(a3), "r"(b0), "r"(b1));
}

__device__ __forceinline__ void mma8(float* c,
        uint32_t a0, uint32_t a1, uint32_t b0) {
    asm volatile(
        "mma.sync.aligned.m16n8k8.row.col.f32.f16.f16.f32 "
        "{%0,%1,%2,%3},{%4,%5},{%6},{%0,%1,%2,%3};\n"
        : "+f"(c[0]), "+f"(c[1]), "+f"(c[2]), "+f"(c[3])
        : "r"(a0), "r"(a1), "r"(b0));
}

__device__ __forceinline__ void cp16(float* s, const float* g) {
    uint32_t sa = (uint32_t)__cvta_generic_to_shared(s);
    asm volatile("cp.async.cg.shared.global [%0], [%1], 16;\n" :: "r"(sa), "l"(g));
}
#define CP_COMMIT asm volatile("cp.async.commit_group;\n" ::: "memory")
#define CP_WAIT0  asm volatile("cp.async.wait_group 0;\n" ::: "memory")

// load a 64-row x 64-col fp32 chunk into smem
__device__ __forceinline__ void load_chunk(float* dst, const float* gb,
                                           int row0, int str, int tid) {
    #pragma unroll
    for (int i = 0; i < 4; i++) {
        int idx = tid + 256 * i;
        int r   = idx >> 4;
        int c4  = (idx & 15) << 2;
        cp16(dst + r * str + c4, gb + (long)(row0 + r) * 512 + c4);
    }
}

__global__ __launch_bounds__(256, 3)
void axial_attn_kernel(const float* __restrict__ q,
                       const float* __restrict__ k,
                       const float* __restrict__ v,
                       const int*   __restrict__ amask,
                       const float* __restrict__ hmask,
                       float* __restrict__ outp,
                       float* __restrict__ attnp)
{
    extern __shared__ float sm[];
    __half* Qs  = (__half*)sm;              // QROWS x QSTRH halves
    float*  KV  = sm + QFLOATS;             // 2 x KVBUF fp32
    float*  red = sm + RED_OFF;             // [2][8cg][16rows]

    const int tid  = threadIdx.x;
    const int cg   = tid >> 5;              // warp = col group (0..7)
    const int lane = tid & 31;
    const int gid  = lane >> 2;
    const int tig  = lane & 3;
    const int cb   = cg * 8 + 2 * tig;      // fragment col base within chunk

    const int Bp    = blockIdx.y;
    const int q0    = blockIdx.x * QROWS;
    const int outer = Bp >> 3;
    const int Wd    = Bp & 7;
    const long base = (long)outer * 262144 + (long)Wd * 64;

    const float* qb = q + base;
    const float* kb = k + base;
    const float* vb = v + base;
    float* ob = outp + base;
    float* ab = attnp + (long)Bp * 262144;

    const int qlo = q0 + gid;
    const int qhi = qlo + 8;

    // kick off K chunk 0 fetch
    load_chunk(KV, kb, 0, KSTR, tid);
    CP_COMMIT;

    // ---- load Q tile (16 rows; scale by 0.125, convert half) ----
    {
        int r  = tid >> 4;
        int c4 = (tid & 15) << 2;
        float4 t = *(const float4*)(qb + (long)(q0 + r) * 512 + c4);
        uint32_t h0 = packh2(t.x * 0.125f, t.y * 0.125f);
        uint32_t h1 = packh2(t.z * 0.125f, t.w * 0.125f);
        *(uint2*)(Qs + r * QSTRH + c4) = make_uint2(h0, h1);
    }
    __syncthreads();

    // ---- preload A fragments (all warps same 16 rows) ----
    uint32_t A[4][4];
    #pragma unroll
    for (int ks = 0; ks < 4; ks++) {
        const __half* qr = Qs + gid * QSTRH + ks * 16 + 2 * tig;
        A[ks][0] = *(const uint32_t*)(qr);
        A[ks][1] = *(const uint32_t*)(qr + 8 * QSTRH);
        A[ks][2] = *(const uint32_t*)(qr + 8);
        A[ks][3] = *(const uint32_t*)(qr + 8 * QSTRH + 8);
    }

    // ---- QK^T: 8 chunks, scores accumulate in registers ----
    float C[8][4];
    #pragma unroll
    for (int kc = 0; kc < 8; kc++)
        #pragma unroll
        for (int i = 0; i < 4; i++) C[kc][i] = 0.f;

    for (int kc = 0; kc < 8; kc++) {
        float* cur = KV + (kc & 1) * KVBUF;
        CP_WAIT0;
        __syncthreads();
        if (kc < 7) {
            load_chunk(KV + ((kc + 1) & 1) * KVBUF, kb, (kc + 1) * 64, KSTR, tid);
            CP_COMMIT;
        } else {
            load_chunk(KV, vb, 0, VSTR, tid);   // prefetch V0, hides under softmax
            CP_COMMIT;
        }
        const float* kr = cur + (cg * 8 + gid) * KSTR + 2 * tig;
        #pragma unroll
        for (int ks = 0; ks < 4; ks++) {
            float2 f0 = *(const float2*)(kr + ks * 16);
            float2 f1 = *(const float2*)(kr + ks * 16 + 8);
            mma16(C[kc], A[ks][0], A[ks][1], A[ks][2], A[ks][3],
                  packh2(f0.x, f0.y), packh2(f1.x, f1.y));
        }
    }

    // ---- mask + row max ----
    const int* mloB = amask + (long)qlo * 512;
    const int* mhiB = amask + (long)qhi * 512;
    float mxl = NEG_INF, mxh = NEG_INF;
    #pragma unroll
    for (int kc = 0; kc < 8; kc++) {
        int col = kc * 64 + cb;
        int2 ml = *(const int2*)(mloB + col);
        int2 mh = *(const int2*)(mhiB + col);
        if (ml.x == 0) C[kc][0] = NEG_INF;
        if (ml.y == 0) C[kc][1] = NEG_INF;
        if (mh.x == 0) C[kc][2] = NEG_INF;
        if (mh.y == 0) C[kc][3] = NEG_INF;
        mxl = fmaxf(mxl, fmaxf(C[kc][0], C[kc][1]));
        mxh = fmaxf(mxh, fmaxf(C[kc][2], C[kc][3]));
    }
    mxl = fmaxf(mxl, __shfl_xor_sync(0xFFFFFFFFu, mxl, 1));
    mxl = fmaxf(mxl, __shfl_xor_sync(0xFFFFFFFFu, mxl, 2));
    mxh = fmaxf(mxh, __shfl_xor_sync(0xFFFFFFFFu, mxh, 1));
    mxh = fmaxf(mxh, __shfl_xor_sync(0xFFFFFFFFu, mxh, 2));
    if (tig == 0) {
        red[cg * 16 + gid]     = mxl;
        red[cg * 16 + gid + 8] = mxh;
    }
    __syncthreads();
    float gml = NEG_INF, gmh = NEG_INF;
    #pragma unroll
    for (int j = 0; j < 8; j++) {
        gml = fmaxf(gml, red[j * 16 + gid]);
        gmh = fmaxf(gmh, red[j * 16 + gid + 8]);
    }

    // ---- exp + row sum ----
    float sl = 0.f, sh = 0.f;
    #pragma unroll
    for (int kc = 0; kc < 8; kc++) {
        float e0 = __expf(C[kc][0] - gml);
        float e1 = __expf(C[kc][1] - gml);
        float e2 = __expf(C[kc][2] - gmh);
        float e3 = __expf(C[kc][3] - gmh);
        C[kc][0] = e0; C[kc][1] = e1; C[kc][2] = e2; C[kc][3] = e3;
        sl += e0 + e1;
        sh += e2 + e3;
    }
    sl += __shfl_xor_sync(0xFFFFFFFFu, sl, 1);
    sl += __shfl_xor_sync(0xFFFFFFFFu, sl, 2);
    sh += __shfl_xor_sync(0xFFFFFFFFu, sh, 1);
    sh += __shfl_xor_sync(0xFFFFFFFFu, sh, 2);
    __syncthreads();   // red max phase done before sum overlay
    if (tig == 0) {
        red[128 + cg * 16 + gid]     = sl;
        red[128 + cg * 16 + gid + 8] = sh;
    }
    __syncthreads();
    float tl = 0.f, th = 0.f;
    #pragma unroll
    for (int j = 0; j < 8; j++) {
        tl += red[128 + j * 16 + gid];
        th += red[128 + j * 16 + gid + 8];
    }
    float invl = 1.0f / tl;
    float invh = 1.0f / th;

    // ---- head_mask, write attn from fragments, pack P (half2) in regs ----
    const float* hloB = hmask + (long)qlo * 512;
    const float* hhiB = hmask + (long)qhi * 512;
    float* aloB = ab + (long)qlo * 512;
    float* ahiB = ab + (long)qhi * 512;
    uint32_t P[8][2];
    #pragma unroll
    for (int kc = 0; kc < 8; kc++) {
        int col = kc * 64 + cb;
        float2 hl = *(const float2*)(hloB + col);
        float2 hh = *(const float2*)(hhiB + col);
        float a0 = C[kc][0] * invl * hl.x;
        float a1 = C[kc][1] * invl * hl.y;
        float a2 = C[kc][2] * invh * hh.x;
        float a3 = C[kc][3] * invh * hh.y;
        *(float2*)(aloB + col) = make_float2(a0, a1);
        *(float2*)(ahiB + col) = make_float2(a2, a3);
        P[kc][0] = packh2(a0, a1);
        P[kc][1] = packh2(a2, a3);
    }

    // ---- PV: per-warp partial O over its 8-k slices (m16n8k8) ----
    float O[8][4];
    #pragma unroll
    for (int nt = 0; nt < 8; nt++)
        #pragma unroll
        for (int i = 0; i < 4; i++) O[nt][i] = 0.f;

    for (int vc = 0; vc < 8; vc++) {
        float* cur = KV + (vc & 1) * KVBUF;
        CP_WAIT0;
        __syncthreads();
        if (vc < 7) {
            load_chunk(KV + ((vc + 1) & 1) * KVBUF, vb, (vc + 1) * 64, VSTR, tid);
            CP_COMMIT;
        }
        uint32_t a0 = P[vc][0], a1 = P[vc][1];
        const float* vrb = cur + (cg * 8 + 2 * tig) * VSTR + gid;
        #pragma unroll
        for (int nt = 0; nt < 8; nt++) {
            uint32_t b0 = packh2(vrb[nt * 8], vrb[VSTR + nt * 8]);
            mma8(O[nt], a0, a1, b0);
        }
    }

    // ---- cross-warp O reduction (8 partials) in freed KV smem ----
    __syncthreads();          // all warps done with KV buffers
    float* Op = KV;           // 8 regions of 16 x OPSTR
    #pragma unroll
    for (int nt = 0; nt < 8; nt++) {
        float* p0 = Op + cg * (16 * OPSTR) + gid * OPSTR + nt * 8 + 2 * tig;
        *(float2*)(p0)              = make_float2(O[nt][0], O[nt][1]);
        *(float2*)(p0 + 8 * OPSTR)  = make_float2(O[nt][2], O[nt][3]);
    }
    __syncthreads();
    {
        int row = tid >> 4;            // 0..15
        int c4  = (tid & 15) << 2;     // 0..60
        float4 s = *(const float4*)(Op + row * OPSTR + c4);
        #pragma unroll
        for (int j = 1; j < 8; j++) {
            float4 t = *(const float4*)(Op + j * (16 * OPSTR) + row * OPSTR + c4);
            s.x += t.x; s.y += t.y; s.z += t.z; s.w += t.w;
        }
        *(float4*)(ob + (long)(q0 + row) * 512 + c4) = s;
    }
}

extern "C" void kernel_launch(void* const* d_in, const int* in_sizes, int n_in,
                              void* d_out, int out_size) {
    const float* q  = (const float*)d_in[0];
    const float* k  = (const float*)d_in[1];
    const float* v  = (const float*)d_in[2];
    const int*   am = (const int*)d_in[3];
    const float* hm = (const float*)d_in[4];

    float* out  = (float*)d_out;
    float* attn = out + (long)in_sizes[0];

    size_t smem = (size_t)SMEM_FLOATS * sizeof(float);
    cudaFuncSetAttribute(axial_attn_kernel,
                         cudaFuncAttributeMaxDynamicSharedMemorySize, (int)smem);

    dim3 grid(32, 512);   // x: 16-row query tiles, y: flattened batch B'
    axial_attn_kernel<<<grid, 256, smem>>>(q, k, v, am, hm, out, attn);
}

// round 6
// speedup vs baseline: 1.6301x; 1.6301x over previous
#include <cuda_runtime.h>
#include <cuda_fp16.h>
#include <cstdint>

// AxialAttention: 512 independent attention problems of [S=512, c=64].
// B' = outer*8 + W; q/k/v/out element (B', s, c) at outer*262144 + s*512 + W*64 + c.
// attn output [B',512,512] contiguous, placed after `out` in d_out.
// R6: fp16 K/V staged in smem (LDG->cvt->STS, register double-buffered),
// ldmatrix.x4 fragment loads, smem scores + P overlay (R3 softmax path).

#define QSTRH 72           // Q smem row stride (halves)
#define BSTRH 72           // K/V buffer row stride (halves)
#define SSTR 516           // scores smem row stride (floats)
#define QROWS 32
#define QS_FLOATS 1152     // 32*72 halves
#define BUF_FLOATS 2304    // 64*72 halves
#define SMEM_FLOATS (QS_FLOATS + BUF_FLOATS + QROWS*SSTR)

__device__ __forceinline__ uint32_t packh2(float a, float b) {
    __half2 h = __floats2half2_rn(a, b);
    return *reinterpret_cast<uint32_t*>(&h);
}

__device__ __forceinline__ void mma16(float* c,
        uint32_t a0, uint32_t a1, uint32_t a2, uint32_t a3,
        uint32_t b0, uint32_t b1) {
    asm volatile(
        "mma.sync.aligned.m16n8k16.row.col.f32.f16.f16.f32 "
        "{%0,%1,%2,%3},{%4,%5,%6,%7},{%8,%9},{%0,%1,%2,%3};\n"
        : "+f"(c[0]), "+f"(c[1]), "+f"(c[2]), "+f"(c[3])
        : "r"(a0), "r"(a1), "r"(a2), "r"(a3), "r"(b0), "r"(b1));
}

__device__ __forceinline__ void ldsm4(uint32_t& r0, uint32_t& r1,
                                      uint32_t& r2, uint32_t& r3, uint32_t a) {
    asm volatile("ldmatrix.sync.aligned.m8n8.x4.shared.b16 {%0,%1,%2,%3}, [%4];\n"
        : "=r"(r0), "=r"(r1), "=r"(r2), "=r"(r3) : "r"(a));
}

__device__ __forceinline__ void ldsm4t(uint32_t& r0, uint32_t& r1,
                                       uint32_t& r2, uint32_t& r3, uint32_t a) {
    asm volatile("ldmatrix.sync.aligned.m8n8.x4.trans.shared.b16 {%0,%1,%2,%3}, [%4];\n"
        : "=r"(r0), "=r"(r1), "=r"(r2), "=r"(r3) : "r"(a));
}

// LDG a 64x64 fp32 chunk into 4 float4 registers (per-thread slice)
__device__ __forceinline__ void ldg_chunk(float4* F, const float* __restrict__ gb,
                                          int row0, int tid) {
    #pragma unroll
    for (int i = 0; i < 4; i++) {
        int e  = tid + 256 * i;
        int r  = e >> 4;
        int c4 = (e & 15) << 2;
        F[i] = *(const float4*)(gb + (long)(row0 + r) * 512 + c4);
    }
}

// convert + store registers into the fp16 buffer
__device__ __forceinline__ void sts_chunk(__half* bufH, const float4* F, int tid) {
    #pragma unroll
    for (int i = 0; i < 4; i++) {
        int e  = tid + 256 * i;
        int r  = e >> 4;
        int c4 = (e & 15) << 2;
        uint32_t h0 = packh2(F[i].x, F[i].y);
        uint32_t h1 = packh2(F[i].z, F[i].w);
        *(uint2*)(bufH + r * BSTRH + c4) = make_uint2(h0, h1);
    }
}

__global__ __launch_bounds__(256, 2)
void axial_attn_kernel(const float* __restrict__ q,
                       const float* __restrict__ k,
                       const float* __restrict__ v,
                       const int*   __restrict__ amask,
                       const float* __restrict__ hmask,
                       float* __restrict__ outp,
                       float* __restrict__ attnp)
{
    extern __shared__ float sm[];
    __half* Qs = (__half*)sm;                   // 32 x 72 halves
    __half* Bh = (__half*)(sm + QS_FLOATS);     // 64 x 72 halves (K/V chunk, fp16)
    float*  Sc = sm + QS_FLOATS + BUF_FLOATS;   // 32 x 516 scores / P overlay

    const int tid  = threadIdx.x;
    const int w    = tid >> 5;
    const int lane = tid & 31;
    const int gid  = lane >> 2;
    const int tig  = lane & 3;
    const int rg   = w >> 2;       // row group (0/1) -> 16 rows
    const int cg   = w & 3;        // col group (0..3) -> 16 cols within chunk
    const int m0   = rg * 16;

    const uint32_t bufaddr = (uint32_t)__cvta_generic_to_shared(Bh);
    // QK^T ldmatrix (no-trans): rows = keys, cols = chans
    const int krow_l   = cg * 16 + ((lane >> 3) & 1) * 8 + (lane & 7);
    const int choff_l  = ((lane >> 4) & 1) * 8;
    const uint32_t kaddr0 = bufaddr + (uint32_t)(krow_l * BSTRH + choff_l) * 2;
    // PV ldmatrix (.trans): rows = keys, cols = chans (warp's 16-chan slice)
    const int vrow_l   = ((lane >> 3) & 1) * 8 + (lane & 7);
    const int vch_l    = cg * 16 + ((lane >> 4) & 1) * 8;
    const uint32_t vaddr0 = bufaddr + (uint32_t)(vrow_l * BSTRH + vch_l) * 2;

    const int Bp    = blockIdx.y;
    const int q0    = blockIdx.x * QROWS;
    const int outer = Bp >> 3;
    const int Wd    = Bp & 7;
    const long base = (long)outer * 262144 + (long)Wd * 64;

    const float* qb = q + base;
    const float* kb = k + base;
    const float* vb = v + base;
    float* ob = outp + base;
    float* ab = attnp + (long)Bp * 262144;

    // ---- prologue: LDG K chunk 0 into regs; stage Q ----
    float4 F[4];
    ldg_chunk(F, kb, 0, tid);

    #pragma unroll
    for (int i = 0; i < 2; i++) {
        int idx = tid + 256 * i;
        int r   = idx >> 4;
        int c4  = (idx & 15) << 2;
        float4 t = *(const float4*)(qb + (long)(q0 + r) * 512 + c4);
        uint32_t h0 = packh2(t.x * 0.125f, t.y * 0.125f);
        uint32_t h1 = packh2(t.z * 0.125f, t.w * 0.125f);
        *(uint2*)(Qs + r * QSTRH + c4) = make_uint2(h0, h1);
    }
    __syncthreads();

    // ---- preload A fragments ----
    uint32_t A[4][4];
    #pragma unroll
    for (int ks = 0; ks < 4; ks++) {
        const __half* qr = Qs + (m0 + gid) * QSTRH + ks * 16 + 2 * tig;
        A[ks][0] = *(const uint32_t*)(qr);
        A[ks][1] = *(const uint32_t*)(qr + 8 * QSTRH);
        A[ks][2] = *(const uint32_t*)(qr + 8);
        A[ks][3] = *(const uint32_t*)(qr + 8 * QSTRH + 8);
    }

    // ---- QK^T over 8 chunks of 64 key rows ----
    for (int kc = 0; kc < 8; kc++) {
        __syncthreads();                 // buffer free (prev chunk MMA done)
        sts_chunk(Bh, F, tid);           // convert current chunk to fp16
        if (kc < 7) ldg_chunk(F, kb, (kc + 1) * 64, tid);   // prefetch next K
        else        ldg_chunk(F, vb, 0, tid);                // prefetch V0
        __syncthreads();                 // conversion visible

        float C[2][4];
        #pragma unroll
        for (int nt = 0; nt < 2; nt++)
            #pragma unroll
            for (int i = 0; i < 4; i++) C[nt][i] = 0.f;

        #pragma unroll
        for (int ks = 0; ks < 4; ks++) {
            uint32_t b0, b1, b2, b3;
            ldsm4(b0, b1, b2, b3, kaddr0 + ks * 32);
            mma16(C[0], A[ks][0], A[ks][1], A[ks][2], A[ks][3], b0, b2);
            mma16(C[1], A[ks][0], A[ks][1], A[ks][2], A[ks][3], b1, b3);
        }
        #pragma unroll
        for (int nt = 0; nt < 2; nt++) {
            int col = kc * 64 + cg * 16 + nt * 8 + tig * 2;
            float* s0 = Sc + (m0 + gid) * SSTR + col;
            *(float2*)(s0)            = make_float2(C[nt][0], C[nt][1]);
            *(float2*)(s0 + 8 * SSTR) = make_float2(C[nt][2], C[nt][3]);
        }
    }
    __syncthreads();

    // ---- masked softmax + head_mask; write attn; store P as half2 overlay ----
    for (int rr = 0; rr < 4; rr++) {
        int r    = w * 4 + rr;
        int qrow = q0 + r;
        float*     srow = Sc + r * SSTR;
        const int* mrow = amask + (long)qrow * 512;

        float sv[16];
        float mx = -INFINITY;
        #pragma unroll
        for (int j = 0; j < 8; j++) {
            int col = 2 * lane + 64 * j;
            float2 s2 = *(const float2*)(srow + col);
            int2   m2 = *(const int2*)(mrow + col);
            float s0 = (m2.x != 0) ? s2.x : -INFINITY;
            float s1 = (m2.y != 0) ? s2.y : -INFINITY;
            sv[2*j]   = s0;
            sv[2*j+1] = s1;
            mx = fmaxf(mx, fmaxf(s0, s1));
        }
        #pragma unroll
        for (int o = 16; o; o >>= 1) mx = fmaxf(mx, __shfl_xor_sync(0xFFFFFFFFu, mx, o));

        float sum = 0.f;
        #pragma unroll
        for (int j = 0; j < 16; j++) {
            float e = __expf(sv[j] - mx);
            sv[j] = e;
            sum += e;
        }
        #pragma unroll
        for (int o = 16; o; o >>= 1) sum += __shfl_xor_sync(0xFFFFFFFFu, sum, o);
        float inv = 1.0f / sum;

        const float* hrow = hmask + (long)qrow * 512;
        float*       arow = ab + (long)qrow * 512;
        __syncwarp();   // all reads of srow done before half overlay writes
        #pragma unroll
        for (int j = 0; j < 8; j++) {
            int col = 2 * lane + 64 * j;
            float2 h2 = *(const float2*)(hrow + col);
            float a0 = sv[2*j]   * inv * h2.x;
            float a1 = sv[2*j+1] * inv * h2.y;
            *(float2*)(arow + col) = make_float2(a0, a1);
            ((uint32_t*)srow)[lane + 32 * j] = packh2(a0, a1);  // P overlay (half2)
        }
    }
    __syncthreads();

    // ---- O = P @ V over 8 chunks (V0 already in regs) ----
    float O[2][4];
    #pragma unroll
    for (int nt = 0; nt < 2; nt++)
        #pragma unroll
        for (int i = 0; i < 4; i++) O[nt][i] = 0.f;

    const uint32_t* Pr0 = (const uint32_t*)(Sc + (m0 + gid) * SSTR);
    const uint32_t* Pr1 = (const uint32_t*)(Sc + (m0 + gid + 8) * SSTR);

    for (int vc = 0; vc < 8; vc++) {
        __syncthreads();                 // buffer free
        sts_chunk(Bh, F, tid);           // convert V chunk to fp16
        if (vc < 7) ldg_chunk(F, vb, (vc + 1) * 64, tid);
        __syncthreads();                 // conversion visible

        #pragma unroll
        for (int ks = 0; ks < 4; ks++) {
            int hidx = vc * 32 + ks * 8 + tig;     // half2 index within P row
            uint32_t a0 = Pr0[hidx];
            uint32_t a1 = Pr1[hidx];
            uint32_t a2 = Pr0[hidx + 4];
            uint32_t a3 = Pr1[hidx + 4];
            uint32_t b0, b1, b2, b3;
            ldsm4t(b0, b1, b2, b3, vaddr0 + ks * (16 * BSTRH * 2));
            mma16(O[0], a0, a1, a2, a3, b0, b1);
            mma16(O[1], a0, a1, a2, a3, b2, b3);
        }
    }

    // ---- write out tile ----
    #pragma unroll
    for (int nt = 0; nt < 2; nt++) {
        int col = cg * 16 + nt * 8 + tig * 2;
        float* o0 = ob + (long)(q0 + m0 + gid) * 512 + col;
        *(float2*)o0 = make_float2(O[nt][0], O[nt][1]);
        float* o1 = ob + (long)(q0 + m0 + gid + 8) * 512 + col;
        *(float2*)o1 = make_float2(O[nt][2], O[nt][3]);
    }
}

extern "C" void kernel_launch(void* const* d_in, const int* in_sizes, int n_in,
                              void* d_out, int out_size) {
    const float* q  = (const float*)d_in[0];
    const float* k  = (const float*)d_in[1];
    const float* v  = (const float*)d_in[2];
    const int*   am = (const int*)d_in[3];
    const float* hm = (const float*)d_in[4];

    float* out  = (float*)d_out;
    float* attn = out + (long)in_sizes[0];

    size_t smem = (size_t)SMEM_FLOATS * sizeof(float);
    cudaFuncSetAttribute(axial_attn_kernel,
                         cudaFuncAttributeMaxDynamicSharedMemorySize, (int)smem);

    dim3 grid(16, 512);   // x: 32-row query tiles, y: flattened batch B'
    axial_attn_kernel<<<grid, 256, smem>>>(q, k, v, am, hm, out, attn);
}